// round 5
// baseline (speedup 1.0000x reference)
#include <cuda_runtime.h>
#include <cuda_fp16.h>
#include <math.h>
#include <stdint.h>

#define KC   256
#define D    512
#define NLOW 130816

// Per-e-block partial squared sums: g_part[j][b][k]
__device__ float g_part[(size_t)4 * 1024 * KC];

__device__ __forceinline__ uint32_t smem_u32(const void* p) {
    uint32_t a;
    asm("{ .reg .u64 t; cvta.to.shared.u64 t, %1; cvt.u32.u64 %0, t; }"
        : "=r"(a) : "l"(p));
    return a;
}
__device__ __forceinline__ uint32_t ldsf(uint32_t a) {
    uint32_t v; asm("ld.shared.b32 %0, [%1];" : "=r"(v) : "r"(a)); return v;
}

// ---------------------------------------------------------------------------
// SMEM layout (dynamic):
//   [0,2048)        Wsm (512 f32)
//   [2048,4096)     red (4 planes x 128 f32)
//   [4096,24576)    A double buffer (2 x 128 rows x 32 halfs, stride 80B)
//   [24576,157696)  B (128 e-rows x KJ d-cols fp16, row stride S=2*KJ+16)
//   [157696,166144) staging tile (64 x 66 halfs)
// ---------------------------------------------------------------------------
#define ROFF   2048
#define AOFF   4096
#define ABUF   10240
#define BOFF   24576
#define SOFF   157696
#define SMEMSZ 166144

__global__ void __launch_bounds__(512)
gml2_fused(const float* __restrict__ X, const float* __restrict__ W,
           const float* __restrict__ diags, const float* __restrict__ lower) {
    extern __shared__ char smem[];
    const int tid = threadIdx.x;
    const int wid = tid >> 5, lid = tid & 31;
    const int k  = blockIdx.x;
    const int j  = blockIdx.y;
    const int e0 = j << 7;
    const int KJ = D - e0;          // 512,384,256,128
    const int nc = KJ >> 5;         // K-chunks of 32
    const uint32_t S = (uint32_t)(KJ * 2 + 16);  // B row stride (== 16 mod 128)

    const uint32_t sb = smem_u32(smem);
    float*  Wsm = (float*)smem;
    float*  red = (float*)(smem + ROFF);
    __half* stg = (__half*)(smem + SOFF);

    for (int i = tid; i < D; i += 512) Wsm[i] = W[(size_t)k * D + i];

    // ---- build B in SMEM: B[e][d] = L_k[d][e], e in [e0,e0+128), d in [e0,512)
    const int ndt = KJ >> 6;
#pragma unroll 1
    for (int et = 0; et < 2; ++et) {
#pragma unroll 1
        for (int dt = 0; dt < ndt; ++dt) {
            const int dg0 = e0 + (dt << 6), eg0 = e0 + (et << 6);
            __syncthreads();
#pragma unroll
            for (int it = 0; it < 8; ++it) {
                const int li = it * 512 + tid;
                const int dl = li >> 6, el = li & 63;
                const int d = dg0 + dl, e = eg0 + el;
                float v = 0.f;
                if (e == d)     { float t = diags[(size_t)k * D + d]; v = t * t; }
                else if (e < d) v = lower[(size_t)k * NLOW +
                                          (((size_t)d * (d - 1)) >> 1) + e];
                stg[el * 66 + dl] = __float2half_rn(v);
            }
            __syncthreads();
#pragma unroll
            for (int it = 0; it < 4; ++it) {
                const int u = it * 512 + tid;
                const int el = u >> 5, w = u & 31;
                const uint32_t val = *(const uint32_t*)&stg[el * 66 + w * 2];
                *(uint32_t*)(smem + BOFF + (size_t)((et << 6) + el) * S +
                             (dt << 7) + w * 4) = val;
            }
        }
    }
    __syncthreads();

    // ---- warp layout: 16 warps, 32x32 tiles over 128x128
    const int m0 = (wid & 3) << 5;
    const int n0 = (wid >> 2) << 5;
    const int gq = lid >> 2, tg = lid & 3;
    const uint32_t aF = sb + AOFF + (m0 + gq) * 80 + tg * 4;
    const uint32_t bF = sb + BOFF + (n0 + gq) * S + tg * 4;

#pragma unroll 1
    for (int bt = 0; bt < 8; ++bt) {
        const int b0 = bt << 7;

        // fill A(0)
#pragma unroll
        for (int it = 0; it < 2; ++it) {
            const int idx = it * 512 + tid;
            const int row = idx >> 3, seg = idx & 7;
            float4 xv = *(const float4*)&X[(size_t)(b0 + row) * D + e0 + seg * 4];
            float4 wv = *(const float4*)&Wsm[e0 + seg * 4];
            __half2 h0 = __floats2half2_rn(xv.x - wv.x, xv.y - wv.y);
            __half2 h1 = __floats2half2_rn(xv.z - wv.z, xv.w - wv.w);
            uint2 u = make_uint2(*(uint32_t*)&h0, *(uint32_t*)&h1);
            *(uint2*)(smem + AOFF + row * 80 + seg * 8) = u;
        }

        float acc[2][4][4];
#pragma unroll
        for (int mt = 0; mt < 2; ++mt)
#pragma unroll
            for (int nt = 0; nt < 4; ++nt)
#pragma unroll
                for (int q = 0; q < 4; ++q) acc[mt][nt][q] = 0.f;

#pragma unroll 1
        for (int c = 0; c < nc; ++c) {
            __syncthreads();

            // prefetch A(c+1) globals
            float4 pa[2];
            const int d0n = e0 + ((c + 1) << 5);
            if (c + 1 < nc) {
#pragma unroll
                for (int it = 0; it < 2; ++it) {
                    const int idx = it * 512 + tid;
                    const int row = idx >> 3, seg = idx & 7;
                    pa[it] = *(const float4*)&X[(size_t)(b0 + row) * D + d0n + seg * 4];
                }
            }

            // compute chunk c
            const uint32_t aB = aF + (c & 1) * ABUF;
            const uint32_t bB = bF + (c << 6);
#pragma unroll
            for (int ks = 0; ks < 2; ++ks) {
                uint32_t a[2][4], b[4][2];
#pragma unroll
                for (int mt = 0; mt < 2; ++mt) {
                    const uint32_t base = aB + mt * (16 * 80) + ks * 32;
                    a[mt][0] = ldsf(base);
                    a[mt][1] = ldsf(base + 8 * 80);
                    a[mt][2] = ldsf(base + 16);
                    a[mt][3] = ldsf(base + 8 * 80 + 16);
                }
#pragma unroll
                for (int nt = 0; nt < 4; ++nt) {
                    const uint32_t base = bB + nt * 8 * S + ks * 32;
                    b[nt][0] = ldsf(base);
                    b[nt][1] = ldsf(base + 16);
                }
#pragma unroll
                for (int mt = 0; mt < 2; ++mt)
#pragma unroll
                    for (int nt = 0; nt < 4; ++nt)
                        asm volatile(
                            "mma.sync.aligned.m16n8k16.row.col.f32.f16.f16.f32 "
                            "{%0,%1,%2,%3},{%4,%5,%6,%7},{%8,%9},{%0,%1,%2,%3};"
                            : "+f"(acc[mt][nt][0]), "+f"(acc[mt][nt][1]),
                              "+f"(acc[mt][nt][2]), "+f"(acc[mt][nt][3])
                            : "r"(a[mt][0]), "r"(a[mt][1]),
                              "r"(a[mt][2]), "r"(a[mt][3]),
                              "r"(b[nt][0]), "r"(b[nt][1]));
            }

            // store A(c+1) into other buffer
            if (c + 1 < nc) {
#pragma unroll
                for (int it = 0; it < 2; ++it) {
                    const int idx = it * 512 + tid;
                    const int row = idx >> 3, seg = idx & 7;
                    float4 wv = *(const float4*)&Wsm[d0n + seg * 4];
                    __half2 h0 = __floats2half2_rn(pa[it].x - wv.x, pa[it].y - wv.y);
                    __half2 h1 = __floats2half2_rn(pa[it].z - wv.z, pa[it].w - wv.w);
                    uint2 u = make_uint2(*(uint32_t*)&h0, *(uint32_t*)&h1);
                    *(uint2*)(smem + AOFF + ((c + 1) & 1) * ABUF + row * 80 + seg * 8) = u;
                }
            }
        }

        // ---- epilogue: per-row sum of squares
        float q[4];
#pragma unroll
        for (int mt = 0; mt < 2; ++mt) {
            float s0 = 0.f, s1 = 0.f;
#pragma unroll
            for (int nt = 0; nt < 4; ++nt) {
                s0 += acc[mt][nt][0] * acc[mt][nt][0] + acc[mt][nt][1] * acc[mt][nt][1];
                s1 += acc[mt][nt][2] * acc[mt][nt][2] + acc[mt][nt][3] * acc[mt][nt][3];
            }
            q[mt * 2 + 0] = s0;   // row m0 + 16*mt + gq
            q[mt * 2 + 1] = s1;   // row m0 + 16*mt + gq + 8
        }
#pragma unroll
        for (int i = 0; i < 4; ++i) {
            q[i] += __shfl_xor_sync(0xffffffffu, q[i], 1);
            q[i] += __shfl_xor_sync(0xffffffffu, q[i], 2);
        }
        __syncthreads();          // prior red readers done; all compute done
        if (tg == 0) {
            const int wn = wid >> 2;
            const int rr = m0 + gq;
            red[wn * 128 + rr +  0] = q[0];
            red[wn * 128 + rr +  8] = q[1];
            red[wn * 128 + rr + 16] = q[2];
            red[wn * 128 + rr + 24] = q[3];
        }
        __syncthreads();
        if (tid < 128) {
            float s = red[tid] + red[128 + tid] + red[256 + tid] + red[384 + tid];
            g_part[((size_t)j * 1024 + b0 + tid) * KC + k] = s;
        }
    }
}

// ---------------------------------------------------------------------------
__global__ void finalize(float* __restrict__ out) {
    const size_t idx = (size_t)blockIdx.x * 256 + threadIdx.x;  // 1024*256
    float s = g_part[idx] + g_part[262144 + idx] +
              g_part[2 * 262144 + idx] + g_part[3 * 262144 + idx];
    out[idx] = sqrtf(s);
}

// ---------------------------------------------------------------------------
extern "C" void kernel_launch(void* const* d_in, const int* in_sizes, int n_in,
                              void* d_out, int out_size) {
    const float* X     = (const float*)d_in[0];  // [1024, 512]
    const float* W     = (const float*)d_in[1];  // [256, 1, 512]
    const float* diags = (const float*)d_in[2];  // [256, 512]
    const float* lower = (const float*)d_in[3];  // [256, 130816]
    float* out = (float*)d_out;                  // [1024, 256]

    cudaFuncSetAttribute(gml2_fused, cudaFuncAttributeMaxDynamicSharedMemorySize,
                         SMEMSZ);
    dim3 grid(KC, 4);
    gml2_fused<<<grid, 512, SMEMSZ>>>(X, W, diags, lower);

    finalize<<<1024, 256>>>(out);
}

// round 6
// speedup vs baseline: 1.5217x; 1.5217x over previous
#include <cuda_runtime.h>
#include <cuda_fp16.h>
#include <math.h>
#include <stdint.h>

#define KC   256
#define D    512
#define NLOW 130816

// Dense transposed L in fp16: g_LTh[k][e][d] = L_k[d][e] (block-lower region).
__device__ __half g_LTh[(size_t)KC * D * D];
// Per-e-block partial squared sums: g_part[j][b][k]
__device__ float g_part[(size_t)4 * 1024 * KC];

__device__ __forceinline__ uint32_t smem_u32(const void* p) {
    uint32_t a;
    asm("{ .reg .u64 t; cvta.to.shared.u64 t, %1; cvt.u32.u64 %0, t; }"
        : "=r"(a) : "l"(p));
    return a;
}
__device__ __forceinline__ void cpasync16(uint32_t dst, const void* src) {
    asm volatile("cp.async.cg.shared.global [%0], [%1], 16;"
                 :: "r"(dst), "l"(src) : "memory");
}
#define LDSM4(r0, r1, r2, r3, addr) \
    asm volatile("ldmatrix.sync.aligned.m8n8.x4.shared.b16 {%0,%1,%2,%3}, [%4];" \
                 : "=r"(r0), "=r"(r1), "=r"(r2), "=r"(r3) : "r"(addr))

// ---------------------------------------------------------------------------
// Build: tiled transpose of packed L into fp16 [k][e][d], 64x64 tiles,
// coalesced reads (e contiguous) and writes (d contiguous).
// Only the 40 tiles per k with block-lower coverage (what the GEMM reads).
// ---------------------------------------------------------------------------
__global__ void __launch_bounds__(256)
build_LTh(const float* __restrict__ diags, const float* __restrict__ lower) {
    __shared__ __half s[64 * 66];
    const int tid = threadIdx.x;
    const int k = blockIdx.x;
    const int y = blockIdx.y;
    int eb, r;
    if (y < 16)      { eb = 0; r = y; }
    else if (y < 28) { eb = 1; r = y - 16; }
    else if (y < 36) { eb = 2; r = y - 28; }
    else             { eb = 3; r = y - 36; }
    const int n  = 8 - 2 * eb;
    const int et = 2 * eb + (r >= n ? 1 : 0);
    const int dt = 2 * eb + (r >= n ? r - n : r);
    const int d0 = dt << 6, e0 = et << 6;

#pragma unroll
    for (int it = 0; it < 16; ++it) {
        const int li = it * 256 + tid;
        const int dl = li >> 6, el = li & 63;
        const int d = d0 + dl, e = e0 + el;
        float v = 0.f;
        if (e == d)      { float t = diags[k * D + d]; v = t * t; }
        else if (e < d)  v = lower[(size_t)k * NLOW + (((size_t)d * (d - 1)) >> 1) + e];
        s[el * 66 + dl] = __float2half_rn(v);
    }
    __syncthreads();
#pragma unroll
    for (int it = 0; it < 8; ++it) {
        const int u = it * 256 + tid;
        const int el = u >> 5, w = u & 31;
        const uint32_t val = *(const uint32_t*)&s[el * 66 + w * 2];
        char* dst = (char*)g_LTh +
                    (((size_t)(k * D + e0 + el)) * D + d0) * 2 + w * 4;
        *(uint32_t*)dst = val;
    }
}

// ---------------------------------------------------------------------------
// Main GEMM (fp16 HMMA + ldmatrix): per (b-tile, k, e-block) CTA,
// P = (X - w_k) @ L_k block, accumulate sum of squares per row.
// SMEM tiles: 128 rows x 32 cols fp16, row stride 80 B (ldmatrix conflict-free).
// ---------------------------------------------------------------------------
#define AOFF   2048
#define ABUF   10240
#define BOFF   (2048 + 2 * 10240)            /* 22528 */
#define BBUF   10240
#define ROFF   (22528 + 3 * 10240)           /* 53248 */
#define SMEMSZ (53248 + 1024)                /* 54272 */

__global__ void __launch_bounds__(256)
gml2_mma(const float* __restrict__ X, const float* __restrict__ W) {
    extern __shared__ char smem[];
    float* Wsm = (float*)smem;
    const int tid = threadIdx.x;
    const int wid = tid >> 5, lid = tid & 31;
    const int b0 = blockIdx.x * 128;
    const int k  = blockIdx.y;
    const int j  = blockIdx.z;
    const int e0 = j << 7;
    const int nc = 16 - (j << 2);            // K-chunks of 32: d in [e0, 512)

    const uint32_t sbase = smem_u32(smem);

    for (int i = tid; i < D; i += 256) Wsm[i] = W[(size_t)k * D + i];
    __syncthreads();

    const __half* LB = &g_LTh[((size_t)k * D + e0) * D];   // [row e][d]

    // ---- prologue: A(0) sync fill (fp16); B(0), B(1) cp.async
    {
#pragma unroll
        for (int it = 0; it < 4; ++it) {
            const int idx = it * 256 + tid;          // 128 rows x 8 segs(8B)
            const int row = idx >> 3, seg = idx & 7;
            float4 xv = *(const float4*)&X[(size_t)(b0 + row) * D + e0 + seg * 4];
            float4 wv = *(const float4*)&Wsm[e0 + seg * 4];
            __half2 h0 = __floats2half2_rn(xv.x - wv.x, xv.y - wv.y);
            __half2 h1 = __floats2half2_rn(xv.z - wv.z, xv.w - wv.w);
            uint2 u = make_uint2(*(uint32_t*)&h0, *(uint32_t*)&h1);
            *(uint2*)(smem + AOFF + row * 80 + seg * 8) = u;
        }
    }
#pragma unroll
    for (int p = 0; p < 2; ++p) {
        const int d0 = e0 + p * 32;
#pragma unroll
        for (int it = 0; it < 2; ++it) {
            const int idx = it * 256 + tid;          // 128 rows x 4 segs(16B)
            const int row = idx >> 2, seg = idx & 3;
            cpasync16(sbase + BOFF + p * BBUF + row * 80 + seg * 16,
                      LB + (size_t)row * D + d0 + seg * 8);
        }
        asm volatile("cp.async.commit_group;" ::: "memory");
    }
    __syncthreads();

    float acc[2][8][4];
#pragma unroll
    for (int mt = 0; mt < 2; ++mt)
#pragma unroll
        for (int nt = 0; nt < 8; ++nt)
#pragma unroll
            for (int q = 0; q < 4; ++q) acc[mt][nt][q] = 0.f;

    const int m0 = (wid & 3) * 32, n0 = (wid >> 2) * 64;
    // ldmatrix lane addresses
    const uint32_t aL = sbase + AOFF + (m0 + (lid & 15)) * 80 + (lid >> 4) * 16;
    const uint32_t bL = sbase + BOFF +
                        (n0 + (lid & 7) + ((lid >> 4) << 3)) * 80 +
                        ((lid >> 3) & 1) * 16;

    for (int c = 0; c < nc; ++c) {
        asm volatile("cp.async.wait_group 1;" ::: "memory");
        __syncthreads();

        // issue B(c+2)
        if (c + 2 < nc) {
            const int d0 = e0 + (c + 2) * 32;
            const uint32_t bd = sbase + BOFF + ((c + 2) % 3) * BBUF;
#pragma unroll
            for (int it = 0; it < 2; ++it) {
                const int idx = it * 256 + tid;
                const int row = idx >> 2, seg = idx & 3;
                cpasync16(bd + row * 80 + seg * 16,
                          LB + (size_t)row * D + d0 + seg * 8);
            }
        }
        asm volatile("cp.async.commit_group;" ::: "memory");

        // prefetch A(c+1) globals
        float4 pa[4];
        const int d0n = e0 + (c + 1) * 32;
        if (c + 1 < nc) {
#pragma unroll
            for (int it = 0; it < 4; ++it) {
                const int idx = it * 256 + tid;
                const int row = idx >> 3, seg = idx & 7;
                pa[it] = *(const float4*)&X[(size_t)(b0 + row) * D + d0n + seg * 4];
            }
        }

        // ---- compute chunk c (fp16 m16n8k16, 2 k-steps, ldmatrix frags)
        const uint32_t aB = aL + (c & 1) * ABUF;
        const uint32_t bB = bL + (c % 3) * BBUF;
#pragma unroll
        for (int ks = 0; ks < 2; ++ks) {
            uint32_t a[2][4], b[8][2];
#pragma unroll
            for (int mt = 0; mt < 2; ++mt)
                LDSM4(a[mt][0], a[mt][1], a[mt][2], a[mt][3],
                      aB + mt * (16 * 80) + ks * 32);
#pragma unroll
            for (int nt2 = 0; nt2 < 4; ++nt2)
                LDSM4(b[nt2 * 2][0], b[nt2 * 2][1],
                      b[nt2 * 2 + 1][0], b[nt2 * 2 + 1][1],
                      bB + nt2 * (16 * 80) + ks * 32);
#pragma unroll
            for (int mt = 0; mt < 2; ++mt)
#pragma unroll
                for (int nt = 0; nt < 8; ++nt)
                    asm volatile(
                        "mma.sync.aligned.m16n8k16.row.col.f32.f16.f16.f32 "
                        "{%0,%1,%2,%3},{%4,%5,%6,%7},{%8,%9},{%0,%1,%2,%3};"
                        : "+f"(acc[mt][nt][0]), "+f"(acc[mt][nt][1]),
                          "+f"(acc[mt][nt][2]), "+f"(acc[mt][nt][3])
                        : "r"(a[mt][0]), "r"(a[mt][1]), "r"(a[mt][2]), "r"(a[mt][3]),
                          "r"(b[nt][0]), "r"(b[nt][1]));
        }

        // store A(c+1) (other buffer)
        if (c + 1 < nc) {
#pragma unroll
            for (int it = 0; it < 4; ++it) {
                const int idx = it * 256 + tid;
                const int row = idx >> 3, seg = idx & 7;
                float4 wv = *(const float4*)&Wsm[d0n + seg * 4];
                __half2 h0 = __floats2half2_rn(pa[it].x - wv.x, pa[it].y - wv.y);
                __half2 h1 = __floats2half2_rn(pa[it].z - wv.z, pa[it].w - wv.w);
                uint2 u = make_uint2(*(uint32_t*)&h0, *(uint32_t*)&h1);
                *(uint2*)(smem + AOFF + ((c + 1) & 1) * ABUF + row * 80 + seg * 8) = u;
            }
        }
    }

    // ---- epilogue: per-row sum of squares
    const int gq = lid >> 2, tg = lid & 3;
    float q[4];
#pragma unroll
    for (int mt = 0; mt < 2; ++mt) {
        float s0 = 0.f, s1 = 0.f;
#pragma unroll
        for (int nt = 0; nt < 8; ++nt) {
            s0 += acc[mt][nt][0] * acc[mt][nt][0] + acc[mt][nt][1] * acc[mt][nt][1];
            s1 += acc[mt][nt][2] * acc[mt][nt][2] + acc[mt][nt][3] * acc[mt][nt][3];
        }
        q[mt * 2 + 0] = s0;   // row m0 + 16*mt + gq
        q[mt * 2 + 1] = s1;   // row m0 + 16*mt + gq + 8
    }
#pragma unroll
    for (int i = 0; i < 4; ++i) {
        q[i] += __shfl_xor_sync(0xffffffffu, q[i], 1);
        q[i] += __shfl_xor_sync(0xffffffffu, q[i], 2);
    }
    float* red = (float*)(smem + ROFF);
    __syncthreads();
    if (tg == 0) {
        const int wn = wid >> 2;
        const int rr = m0 + gq;
        red[wn * 128 + rr +  0] = q[0];
        red[wn * 128 + rr +  8] = q[1];
        red[wn * 128 + rr + 16] = q[2];
        red[wn * 128 + rr + 24] = q[3];
    }
    __syncthreads();
    if (tid < 128) {
        float s = red[tid] + red[128 + tid];
        g_part[((size_t)j * 1024 + b0 + tid) * KC + k] = s;
    }
}

// ---------------------------------------------------------------------------
__global__ void finalize(float* __restrict__ out) {
    const size_t idx = (size_t)blockIdx.x * 256 + threadIdx.x;  // 1024*256
    float s = g_part[idx] + g_part[262144 + idx] +
              g_part[2 * 262144 + idx] + g_part[3 * 262144 + idx];
    out[idx] = sqrtf(s);
}

// ---------------------------------------------------------------------------
extern "C" void kernel_launch(void* const* d_in, const int* in_sizes, int n_in,
                              void* d_out, int out_size) {
    const float* X     = (const float*)d_in[0];  // [1024, 512]
    const float* W     = (const float*)d_in[1];  // [256, 1, 512]
    const float* diags = (const float*)d_in[2];  // [256, 512]
    const float* lower = (const float*)d_in[3];  // [256, 130816]
    float* out = (float*)d_out;                  // [1024, 256]

    build_LTh<<<dim3(KC, 40), 256>>>(diags, lower);

    cudaFuncSetAttribute(gml2_mma, cudaFuncAttributeMaxDynamicSharedMemorySize,
                         SMEMSZ);
    dim3 grid(8, KC, 4);
    gml2_mma<<<grid, 256, SMEMSZ>>>(X, W);

    finalize<<<1024, 256>>>(out);
}

// round 7
// speedup vs baseline: 1.5554x; 1.0221x over previous
#include <cuda_runtime.h>
#include <cuda_fp16.h>
#include <math.h>
#include <stdint.h>

#define KC   256
#define D    512
#define NLOW 130816

// Dense L in fp16, natural orientation: g_Lh[k][d][e] = L_k[d][e].
__device__ __half g_Lh[(size_t)KC * D * D];
// Per-e-block partial squared sums: g_part[j][b][k]
__device__ float g_part[(size_t)4 * 1024 * KC];

__device__ __forceinline__ uint32_t smem_u32(const void* p) {
    uint32_t a;
    asm("{ .reg .u64 t; cvta.to.shared.u64 t, %1; cvt.u32.u64 %0, t; }"
        : "=r"(a) : "l"(p));
    return a;
}
__device__ __forceinline__ void cpasync16(uint32_t dst, const void* src) {
    asm volatile("cp.async.cg.shared.global [%0], [%1], 16;"
                 :: "r"(dst), "l"(src) : "memory");
}
#define LDSM4(r0, r1, r2, r3, addr) \
    asm volatile("ldmatrix.sync.aligned.m8n8.x4.shared.b16 {%0,%1,%2,%3}, [%4];" \
                 : "=r"(r0), "=r"(r1), "=r"(r2), "=r"(r3) : "r"(addr))
#define LDSM4T(r0, r1, r2, r3, addr) \
    asm volatile("ldmatrix.sync.aligned.m8n8.x4.trans.shared.b16 {%0,%1,%2,%3}, [%4];" \
                 : "=r"(r0), "=r"(r1), "=r"(r2), "=r"(r3) : "r"(addr))

// ---------------------------------------------------------------------------
// Build: pure streaming expansion of packed L into fp16 [k][d][e].
// Coalesced lower reads (e contiguous) and half2 writes. No SMEM, no syncs.
// Rows with d < (e-block start) are never read by the GEMM -> skipped.
// ---------------------------------------------------------------------------
__global__ void __launch_bounds__(256)
build_Lh(const float* __restrict__ diags, const float* __restrict__ lower) {
    const size_t i = (size_t)blockIdx.x * 256 + threadIdx.x;  // KC*D*D/2
    const int ep = ((int)(i & 255)) << 1;        // e, e+1
    const size_t kd = i >> 8;                    // k*D + d
    const int d  = (int)(kd & 511);
    const int kk = (int)(kd >> 9);
    if (d < ((ep >> 7) << 7)) return;            // never-read region
    const float* rowp = lower + (size_t)kk * NLOW + (((size_t)d * (d - 1)) >> 1);
    float dg = diags[kd];
    float v0 = (ep     < d) ? rowp[ep]     : ((ep     == d) ? dg * dg : 0.f);
    float v1 = (ep + 1 < d) ? rowp[ep + 1] : ((ep + 1 == d) ? dg * dg : 0.f);
    __half2 h = __floats2half2_rn(v0, v1);
    *(uint32_t*)((char*)g_Lh + (kd * D + ep) * 2) = *(uint32_t*)&h;
}

// ---------------------------------------------------------------------------
// Main GEMM (fp16 HMMA + ldmatrix/.trans): per (b-tile, k, e-block) CTA,
// P = (X - w_k) @ L_k block, accumulate sum of squares per row.
// A tiles: 128 rows x 32 halfs, stride 80 B. B tiles: 32 d-rows x 128 e-halfs,
// stride 272 B (ldmatrix conflict-free). 64-granular triangular warp skip.
// ---------------------------------------------------------------------------
#define ROFF   2048
#define AOFF   4096
#define ABUF   10240
#define BOFF   24576                        /* 4096 + 2*10240 */
#define BBUF   8704                         /* 32 * 272 */
#define SMEMSZ (24576 + 3 * 8704)           /* 50688 */

__global__ void __launch_bounds__(256)
gml2_mma(const float* __restrict__ X, const float* __restrict__ W) {
    extern __shared__ char smem[];
    float* Wsm = (float*)smem;
    const int tid = threadIdx.x;
    const int wid = tid >> 5, lid = tid & 31;
    const int b0 = blockIdx.x * 128;
    const int k  = blockIdx.y;
    const int j  = blockIdx.z;
    const int e0 = j << 7;
    const int nc = 16 - (j << 2);            // K-chunks of 32: d in [e0, 512)

    const uint32_t sbase = smem_u32(smem);

    for (int i = tid; i < D; i += 256) Wsm[i] = W[(size_t)k * D + i];
    __syncthreads();

    const __half* Bk = g_Lh + (size_t)k * D * D;   // [d][e]

    // ---- prologue: A(0) sync fill (fp16); B(0), B(1) cp.async
    {
#pragma unroll
        for (int it = 0; it < 4; ++it) {
            const int idx = it * 256 + tid;          // 128 rows x 8 segs(8B)
            const int row = idx >> 3, seg = idx & 7;
            float4 xv = *(const float4*)&X[(size_t)(b0 + row) * D + e0 + seg * 4];
            float4 wv = *(const float4*)&Wsm[e0 + seg * 4];
            __half2 h0 = __floats2half2_rn(xv.x - wv.x, xv.y - wv.y);
            __half2 h1 = __floats2half2_rn(xv.z - wv.z, xv.w - wv.w);
            uint2 u = make_uint2(*(uint32_t*)&h0, *(uint32_t*)&h1);
            *(uint2*)(smem + AOFF + row * 80 + seg * 8) = u;
        }
    }
#pragma unroll
    for (int p = 0; p < 2; ++p) {
        const int d0 = e0 + p * 32;
#pragma unroll
        for (int it = 0; it < 2; ++it) {
            const int idx = it * 256 + tid;          // 32 rows x 16 segs(16B)
            const int rl = idx >> 4, seg = idx & 15;
            cpasync16(sbase + BOFF + p * BBUF + rl * 272 + seg * 16,
                      Bk + (size_t)(d0 + rl) * D + e0 + seg * 8);
        }
        asm volatile("cp.async.commit_group;" ::: "memory");
    }
    __syncthreads();

    float acc[2][8][4];
#pragma unroll
    for (int mt = 0; mt < 2; ++mt)
#pragma unroll
        for (int nt = 0; nt < 8; ++nt)
#pragma unroll
            for (int q = 0; q < 4; ++q) acc[mt][nt][q] = 0.f;

    const int m0 = (wid & 3) * 32, n0 = (wid >> 2) * 64;
    // ldmatrix lane addresses
    const uint32_t aL = sbase + AOFF + (m0 + (lid & 15)) * 80 + (lid >> 4) * 16;
    const uint32_t bL = sbase + BOFF + (lid & 15) * 272 + (lid >> 4) * 16 + n0 * 2;

    for (int c = 0; c < nc; ++c) {
        asm volatile("cp.async.wait_group 1;" ::: "memory");
        __syncthreads();

        // issue B(c+2)
        if (c + 2 < nc) {
            const int d0 = e0 + (c + 2) * 32;
            const uint32_t bd = sbase + BOFF + ((c + 2) % 3) * BBUF;
#pragma unroll
            for (int it = 0; it < 2; ++it) {
                const int idx = it * 256 + tid;
                const int rl = idx >> 4, seg = idx & 15;
                cpasync16(bd + rl * 272 + seg * 16,
                          Bk + (size_t)(d0 + rl) * D + e0 + seg * 8);
            }
        }
        asm volatile("cp.async.commit_group;" ::: "memory");

        // prefetch A(c+1) globals
        float4 pa[4];
        const int d0n = e0 + (c + 1) * 32;
        if (c + 1 < nc) {
#pragma unroll
            for (int it = 0; it < 4; ++it) {
                const int idx = it * 256 + tid;
                const int row = idx >> 3, seg = idx & 7;
                pa[it] = *(const float4*)&X[(size_t)(b0 + row) * D + d0n + seg * 4];
            }
        }

        // ---- compute chunk c; 64-granular triangular skip:
        // warps with n0=64 have e >= e0+64 > d0+31 for c < 2 -> exact zeros.
        if (!(n0 == 64 && c < 2)) {
            const uint32_t aB = aL + (c & 1) * ABUF;
            const uint32_t bB = bL + (c % 3) * BBUF;
#pragma unroll
            for (int ks = 0; ks < 2; ++ks) {
                uint32_t a[2][4], b[8][2];
#pragma unroll
                for (int mt = 0; mt < 2; ++mt)
                    LDSM4(a[mt][0], a[mt][1], a[mt][2], a[mt][3],
                          aB + mt * (16 * 80) + ks * 32);
#pragma unroll
                for (int nt2 = 0; nt2 < 4; ++nt2)
                    LDSM4T(b[nt2 * 2][0], b[nt2 * 2][1],
                           b[nt2 * 2 + 1][0], b[nt2 * 2 + 1][1],
                           bB + ks * (16 * 272) + nt2 * 32);
#pragma unroll
                for (int mt = 0; mt < 2; ++mt)
#pragma unroll
                    for (int nt = 0; nt < 8; ++nt)
                        asm volatile(
                            "mma.sync.aligned.m16n8k16.row.col.f32.f16.f16.f32 "
                            "{%0,%1,%2,%3},{%4,%5,%6,%7},{%8,%9},{%0,%1,%2,%3};"
                            : "+f"(acc[mt][nt][0]), "+f"(acc[mt][nt][1]),
                              "+f"(acc[mt][nt][2]), "+f"(acc[mt][nt][3])
                            : "r"(a[mt][0]), "r"(a[mt][1]),
                              "r"(a[mt][2]), "r"(a[mt][3]),
                              "r"(b[nt][0]), "r"(b[nt][1]));
            }
        }

        // store A(c+1) (other buffer)
        if (c + 1 < nc) {
#pragma unroll
            for (int it = 0; it < 4; ++it) {
                const int idx = it * 256 + tid;
                const int row = idx >> 3, seg = idx & 7;
                float4 wv = *(const float4*)&Wsm[d0n + seg * 4];
                __half2 h0 = __floats2half2_rn(pa[it].x - wv.x, pa[it].y - wv.y);
                __half2 h1 = __floats2half2_rn(pa[it].z - wv.z, pa[it].w - wv.w);
                uint2 u = make_uint2(*(uint32_t*)&h0, *(uint32_t*)&h1);
                *(uint2*)(smem + AOFF + ((c + 1) & 1) * ABUF + row * 80 + seg * 8) = u;
            }
        }
    }

    // ---- epilogue: per-row sum of squares
    const int gq = lid >> 2, tg = lid & 3;
    float q[4];
#pragma unroll
    for (int mt = 0; mt < 2; ++mt) {
        float s0 = 0.f, s1 = 0.f;
#pragma unroll
        for (int nt = 0; nt < 8; ++nt) {
            s0 += acc[mt][nt][0] * acc[mt][nt][0] + acc[mt][nt][1] * acc[mt][nt][1];
            s1 += acc[mt][nt][2] * acc[mt][nt][2] + acc[mt][nt][3] * acc[mt][nt][3];
        }
        q[mt * 2 + 0] = s0;   // row m0 + 16*mt + gq
        q[mt * 2 + 1] = s1;   // row m0 + 16*mt + gq + 8
    }
#pragma unroll
    for (int i = 0; i < 4; ++i) {
        q[i] += __shfl_xor_sync(0xffffffffu, q[i], 1);
        q[i] += __shfl_xor_sync(0xffffffffu, q[i], 2);
    }
    float* red = (float*)(smem + ROFF);
    __syncthreads();
    if (tg == 0) {
        const int wn = wid >> 2;
        const int rr = m0 + gq;
        red[wn * 128 + rr +  0] = q[0];
        red[wn * 128 + rr +  8] = q[1];
        red[wn * 128 + rr + 16] = q[2];
        red[wn * 128 + rr + 24] = q[3];
    }
    __syncthreads();
    if (tid < 128) {
        float s = red[tid] + red[128 + tid];
        g_part[((size_t)j * 1024 + b0 + tid) * KC + k] = s;
    }
}

// ---------------------------------------------------------------------------
__global__ void finalize(float* __restrict__ out) {
    const size_t idx = (size_t)blockIdx.x * 256 + threadIdx.x;  // 1024*256
    float s = g_part[idx] + g_part[262144 + idx] +
              g_part[2 * 262144 + idx] + g_part[3 * 262144 + idx];
    out[idx] = sqrtf(s);
}

// ---------------------------------------------------------------------------
extern "C" void kernel_launch(void* const* d_in, const int* in_sizes, int n_in,
                              void* d_out, int out_size) {
    const float* X     = (const float*)d_in[0];  // [1024, 512]
    const float* W     = (const float*)d_in[1];  // [256, 1, 512]
    const float* diags = (const float*)d_in[2];  // [256, 512]
    const float* lower = (const float*)d_in[3];  // [256, 130816]
    float* out = (float*)d_out;                  // [1024, 256]

    build_Lh<<<(KC * D * D / 2) / 256, 256>>>(diags, lower);

    cudaFuncSetAttribute(gml2_mma, cudaFuncAttributeMaxDynamicSharedMemorySize,
                         SMEMSZ);
    dim3 grid(8, KC, 4);
    gml2_mma<<<grid, 256, SMEMSZ>>>(X, W);

    finalize<<<1024, 256>>>(out);
}

// round 8
// speedup vs baseline: 1.7387x; 1.1178x over previous
#include <cuda_runtime.h>
#include <cuda_fp16.h>
#include <math.h>
#include <stdint.h>

#define KC   256
#define D    512
#define NLOW 130816

// Dense L in fp16, natural orientation: g_Lh[k][d][e] = L_k[d][e].
__device__ __half g_Lh[(size_t)KC * D * D];
// X in fp16.
__device__ __half g_Xh[(size_t)1024 * D];
// wL[k][e] = sum_d w_k[d] * Lh_k[d][e]  (fp32)
__device__ float g_wL[(size_t)KC * D];
// Per-e-block partial squared sums: g_part[j][b][k]
__device__ float g_part[(size_t)4 * 1024 * KC];

__device__ __forceinline__ uint32_t smem_u32(const void* p) {
    uint32_t a;
    asm("{ .reg .u64 t; cvta.to.shared.u64 t, %1; cvt.u32.u64 %0, t; }"
        : "=r"(a) : "l"(p));
    return a;
}
__device__ __forceinline__ void cpasync16(uint32_t dst, const void* src) {
    asm volatile("cp.async.cg.shared.global [%0], [%1], 16;"
                 :: "r"(dst), "l"(src) : "memory");
}
#define LDSM4(r0, r1, r2, r3, addr) \
    asm volatile("ldmatrix.sync.aligned.m8n8.x4.shared.b16 {%0,%1,%2,%3}, [%4];" \
                 : "=r"(r0), "=r"(r1), "=r"(r2), "=r"(r3) : "r"(addr))
#define LDSM4T(r0, r1, r2, r3, addr) \
    asm volatile("ldmatrix.sync.aligned.m8n8.x4.trans.shared.b16 {%0,%1,%2,%3}, [%4];" \
                 : "=r"(r0), "=r"(r1), "=r"(r2), "=r"(r3) : "r"(addr))

// ---------------------------------------------------------------------------
// build_Lh: streaming expansion of packed L into fp16 [k][d][e], MLP=8.
// Rows with d < (e-block start) are never read downstream -> skipped.
// ---------------------------------------------------------------------------
__global__ void __launch_bounds__(256)
build_Lh(const float* __restrict__ diags, const float* __restrict__ lower) {
    const size_t i = (size_t)blockIdx.x * 256 + threadIdx.x;  // KC*D*64
    const int ep = ((int)(i & 63)) << 3;         // e..e+7
    const size_t kd = i >> 6;                    // k*D + d
    const int d  = (int)(kd & 511);
    const int kk = (int)(kd >> 9);
    if (d < ((ep >> 7) << 7)) return;            // never-read region
    const float* rowp = lower + (size_t)kk * NLOW + (((size_t)d * (d - 1)) >> 1);
    float v[8];
#pragma unroll
    for (int t = 0; t < 8; ++t) {
        const int e = ep + t;
        v[t] = (e < d) ? rowp[e] : 0.f;
    }
    if (d >= ep && d < ep + 8) { float t = diags[kd]; v[d - ep] = t * t; }
    uint4 u;
    __half2 h;
    h = __floats2half2_rn(v[0], v[1]); u.x = *(uint32_t*)&h;
    h = __floats2half2_rn(v[2], v[3]); u.y = *(uint32_t*)&h;
    h = __floats2half2_rn(v[4], v[5]); u.z = *(uint32_t*)&h;
    h = __floats2half2_rn(v[6], v[7]); u.w = *(uint32_t*)&h;
    *(uint4*)((char*)g_Lh + (kd * D + ep) * 2) = u;
}

// ---------------------------------------------------------------------------
__global__ void __launch_bounds__(256)
build_Xh(const float* __restrict__ X) {
    const int i = (blockIdx.x * 256 + threadIdx.x) * 4;   // 1024*512
    float4 x = *(const float4*)&X[i];
    __half2 h0 = __floats2half2_rn(x.x, x.y);
    __half2 h1 = __floats2half2_rn(x.z, x.w);
    *(uint2*)((char*)g_Xh + i * 2) = make_uint2(*(uint32_t*)&h0, *(uint32_t*)&h1);
}

// ---------------------------------------------------------------------------
// build_wL: wL[k][e] = sum_{d >= eblock(e)} w[d] * Lh[k][d][e]  (fp32).
// Coalesced over e; unrolled for MLP.
// ---------------------------------------------------------------------------
__global__ void __launch_bounds__(512)
build_wL(const float* __restrict__ W) {
    __shared__ float ws[512];
    const int k = blockIdx.x, e = threadIdx.x;
    ws[e] = W[(size_t)k * D + e];
    __syncthreads();
    const __half* Lk = g_Lh + (size_t)k * D * D;
    float s = 0.f;
    const int dstart = (e >> 7) << 7;
#pragma unroll 4
    for (int d = dstart; d < D; ++d)
        s += ws[d] * __half2float(Lk[(size_t)d * D + e]);
    g_wL[(size_t)k * D + e] = s;
}

// ---------------------------------------------------------------------------
// Main GEMM (fp16 HMMA, pure cp.async streams): per (b-tile, k, e-block) CTA,
// Q = Xh @ Lh block; epilogue squares (Q - wL[e]) and row-reduces.
// A tiles: 128 rows x 32 halfs, stride 80 B. B tiles: 32 d-rows x 128 e-halfs,
// stride 272 B. 4-stage pipeline, one commit group (A+B) per chunk.
// ---------------------------------------------------------------------------
#define ROFF   0
#define WLOFF  2048
#define AOFF   4096
#define ABUF   10240
#define BOFF   (4096 + 4 * 10240)            /* 45056 */
#define BBUF   8704                          /* 32 * 272 */
#define SMEMSZ (45056 + 4 * 8704)            /* 79872 */

__global__ void __launch_bounds__(256, 2)
gml2_mma() {
    extern __shared__ char smem[];
    const int tid = threadIdx.x;
    const int wid = tid >> 5, lid = tid & 31;
    const int b0 = blockIdx.x * 128;
    const int k  = blockIdx.y;
    const int j  = blockIdx.z;
    const int e0 = j << 7;
    const int nc = 16 - (j << 2);            // K-chunks of 32: d in [e0, 512)

    const uint32_t sbase = smem_u32(smem);
    float* wLs = (float*)(smem + WLOFF);
    if (tid < 128) wLs[tid] = g_wL[(size_t)k * D + e0 + tid];

    const __half* Bk = g_Lh + (size_t)k * D * D;   // [d][e]
    const __half* Ab = g_Xh + (size_t)b0 * D;

    // ---- prologue: issue chunks 0,1,2 (A+B each, one group per chunk)
#pragma unroll
    for (int p = 0; p < 3; ++p) {
        const int d0 = e0 + p * 32;
#pragma unroll
        for (int it = 0; it < 2; ++it) {     // A: 128 rows x 4 segs(16B)
            const int idx = it * 256 + tid;
            const int row = idx >> 2, seg = idx & 3;
            cpasync16(sbase + AOFF + p * ABUF + row * 80 + seg * 16,
                      Ab + (size_t)row * D + d0 + seg * 8);
        }
#pragma unroll
        for (int it = 0; it < 2; ++it) {     // B: 32 rows x 16 segs(16B)
            const int idx = it * 256 + tid;
            const int rl = idx >> 4, seg = idx & 15;
            cpasync16(sbase + BOFF + p * BBUF + rl * 272 + seg * 16,
                      Bk + (size_t)(d0 + rl) * D + e0 + seg * 8);
        }
        asm volatile("cp.async.commit_group;" ::: "memory");
    }

    float acc[2][8][4];
#pragma unroll
    for (int mt = 0; mt < 2; ++mt)
#pragma unroll
        for (int nt = 0; nt < 8; ++nt)
#pragma unroll
            for (int q = 0; q < 4; ++q) acc[mt][nt][q] = 0.f;

    const int m0 = (wid & 3) * 32, n0 = (wid >> 2) * 64;
    const uint32_t aL = sbase + AOFF + (m0 + (lid & 15)) * 80 + (lid >> 4) * 16;
    const uint32_t bL = sbase + BOFF + (lid & 15) * 272 + (lid >> 4) * 16 + n0 * 2;

    for (int c = 0; c < nc; ++c) {
        asm volatile("cp.async.wait_group 2;" ::: "memory");
        __syncthreads();

        // issue chunk c+3 into stage (c+3)&3
        if (c + 3 < nc) {
            const int d0 = e0 + (c + 3) * 32;
            const int st = (c + 3) & 3;
#pragma unroll
            for (int it = 0; it < 2; ++it) {
                const int idx = it * 256 + tid;
                const int row = idx >> 2, seg = idx & 3;
                cpasync16(sbase + AOFF + st * ABUF + row * 80 + seg * 16,
                          Ab + (size_t)row * D + d0 + seg * 8);
            }
#pragma unroll
            for (int it = 0; it < 2; ++it) {
                const int idx = it * 256 + tid;
                const int rl = idx >> 4, seg = idx & 15;
                cpasync16(sbase + BOFF + st * BBUF + rl * 272 + seg * 16,
                          Bk + (size_t)(d0 + rl) * D + e0 + seg * 8);
            }
        }
        asm volatile("cp.async.commit_group;" ::: "memory");

        // ---- compute chunk c; triangular warp skip (B block exactly zero)
        if (!(n0 == 64 && c < 2)) {
            const int st = c & 3;
            const uint32_t aB = aL + st * ABUF;
            const uint32_t bB = bL + st * BBUF;
#pragma unroll
            for (int ks = 0; ks < 2; ++ks) {
                uint32_t a[2][4], b[8][2];
#pragma unroll
                for (int mt = 0; mt < 2; ++mt)
                    LDSM4(a[mt][0], a[mt][1], a[mt][2], a[mt][3],
                          aB + mt * (16 * 80) + ks * 32);
#pragma unroll
                for (int nt2 = 0; nt2 < 4; ++nt2)
                    LDSM4T(b[nt2 * 2][0], b[nt2 * 2][1],
                           b[nt2 * 2 + 1][0], b[nt2 * 2 + 1][1],
                           bB + ks * (16 * 272) + nt2 * 32);
#pragma unroll
                for (int mt = 0; mt < 2; ++mt)
#pragma unroll
                    for (int nt = 0; nt < 8; ++nt)
                        asm volatile(
                            "mma.sync.aligned.m16n8k16.row.col.f32.f16.f16.f32 "
                            "{%0,%1,%2,%3},{%4,%5,%6,%7},{%8,%9},{%0,%1,%2,%3};"
                            : "+f"(acc[mt][nt][0]), "+f"(acc[mt][nt][1]),
                              "+f"(acc[mt][nt][2]), "+f"(acc[mt][nt][3])
                            : "r"(a[mt][0]), "r"(a[mt][1]),
                              "r"(a[mt][2]), "r"(a[mt][3]),
                              "r"(b[nt][0]), "r"(b[nt][1]));
            }
        }
    }

    // ---- epilogue: subtract wL, square, row-reduce
    const int gq = lid >> 2, tg = lid & 3;
    float q[4];
#pragma unroll
    for (int mt = 0; mt < 2; ++mt) {
        float s0 = 0.f, s1 = 0.f;
#pragma unroll
        for (int nt = 0; nt < 8; ++nt) {
            const int c0 = n0 + nt * 8 + tg * 2;
            const float wl0 = wLs[c0], wl1 = wLs[c0 + 1];
            float p0 = acc[mt][nt][0] - wl0;
            float p1 = acc[mt][nt][1] - wl1;
            float p2 = acc[mt][nt][2] - wl0;
            float p3 = acc[mt][nt][3] - wl1;
            s0 += p0 * p0 + p1 * p1;
            s1 += p2 * p2 + p3 * p3;
        }
        q[mt * 2 + 0] = s0;   // row m0 + 16*mt + gq
        q[mt * 2 + 1] = s1;   // row m0 + 16*mt + gq + 8
    }
#pragma unroll
    for (int i = 0; i < 4; ++i) {
        q[i] += __shfl_xor_sync(0xffffffffu, q[i], 1);
        q[i] += __shfl_xor_sync(0xffffffffu, q[i], 2);
    }
    float* red = (float*)(smem + ROFF);
    __syncthreads();
    if (tg == 0) {
        const int wn = wid >> 2;
        const int rr = m0 + gq;
        red[wn * 128 + rr +  0] = q[0];
        red[wn * 128 + rr +  8] = q[1];
        red[wn * 128 + rr + 16] = q[2];
        red[wn * 128 + rr + 24] = q[3];
    }
    __syncthreads();
    if (tid < 128) {
        float s = red[tid] + red[128 + tid];
        g_part[((size_t)j * 1024 + b0 + tid) * KC + k] = s;
    }
}

// ---------------------------------------------------------------------------
__global__ void finalize(float* __restrict__ out) {
    const size_t idx = (size_t)blockIdx.x * 256 + threadIdx.x;  // 1024*256
    float s = g_part[idx] + g_part[262144 + idx] +
              g_part[2 * 262144 + idx] + g_part[3 * 262144 + idx];
    out[idx] = sqrtf(s);
}

// ---------------------------------------------------------------------------
extern "C" void kernel_launch(void* const* d_in, const int* in_sizes, int n_in,
                              void* d_out, int out_size) {
    const float* X     = (const float*)d_in[0];  // [1024, 512]
    const float* W     = (const float*)d_in[1];  // [256, 1, 512]
    const float* diags = (const float*)d_in[2];  // [256, 512]
    const float* lower = (const float*)d_in[3];  // [256, 130816]
    float* out = (float*)d_out;                  // [1024, 256]

    build_Lh<<<(KC * D * 64) / 256, 256>>>(diags, lower);
    build_Xh<<<(1024 * D / 4) / 256, 256>>>(X);
    build_wL<<<KC, 512>>>(W);

    cudaFuncSetAttribute(gml2_mma, cudaFuncAttributeMaxDynamicSharedMemorySize,
                         SMEMSZ);
    dim3 grid(8, KC, 4);
    gml2_mma<<<grid, 256, SMEMSZ>>>();

    finalize<<<1024, 256>>>(out);
}

// round 9
// speedup vs baseline: 1.8628x; 1.0714x over previous
#include <cuda_runtime.h>
#include <cuda_fp16.h>
#include <math.h>
#include <stdint.h>

#define KC   256
#define D    512
#define NLOW 130816

// Dense L in fp16, natural orientation: g_Lh[k][d][e] = L_k[d][e].
__device__ __half g_Lh[(size_t)KC * D * D];
// X in fp16.
__device__ __half g_Xh[(size_t)1024 * D];
// wL[k][e] = sum_d w_k[d] * Lh_k[d][e]  (fp32)
__device__ float g_wL[(size_t)KC * D];
// Per-e-block partial squared sums: g_part[j][b][k]
__device__ float g_part[(size_t)4 * 1024 * KC];

__device__ __forceinline__ uint32_t smem_u32(const void* p) {
    uint32_t a;
    asm("{ .reg .u64 t; cvta.to.shared.u64 t, %1; cvt.u32.u64 %0, t; }"
        : "=r"(a) : "l"(p));
    return a;
}
__device__ __forceinline__ void cpasync16(uint32_t dst, const void* src) {
    asm volatile("cp.async.cg.shared.global [%0], [%1], 16;"
                 :: "r"(dst), "l"(src) : "memory");
}
#define LDSM4(r0, r1, r2, r3, addr) \
    asm volatile("ldmatrix.sync.aligned.m8n8.x4.shared.b16 {%0,%1,%2,%3}, [%4];" \
                 : "=r"(r0), "=r"(r1), "=r"(r2), "=r"(r3) : "r"(addr))
#define LDSM4T(r0, r1, r2, r3, addr) \
    asm volatile("ldmatrix.sync.aligned.m8n8.x4.trans.shared.b16 {%0,%1,%2,%3}, [%4];" \
                 : "=r"(r0), "=r"(r1), "=r"(r2), "=r"(r3) : "r"(addr))

// ---------------------------------------------------------------------------
// build_Lh: streaming expansion of packed L into fp16 [k][d][e], MLP=8.
// ---------------------------------------------------------------------------
__global__ void __launch_bounds__(256)
build_Lh(const float* __restrict__ diags, const float* __restrict__ lower) {
    const size_t i = (size_t)blockIdx.x * 256 + threadIdx.x;  // KC*D*64
    const int ep = ((int)(i & 63)) << 3;         // e..e+7
    const size_t kd = i >> 6;                    // k*D + d
    const int d  = (int)(kd & 511);
    const int kk = (int)(kd >> 9);
    if (d < ((ep >> 7) << 7)) return;            // never-read region
    const float* rowp = lower + (size_t)kk * NLOW + (((size_t)d * (d - 1)) >> 1);
    float v[8];
#pragma unroll
    for (int t = 0; t < 8; ++t) {
        const int e = ep + t;
        v[t] = (e < d) ? rowp[e] : 0.f;
    }
    if (d >= ep && d < ep + 8) { float t = diags[kd]; v[d - ep] = t * t; }
    uint4 u;
    __half2 h;
    h = __floats2half2_rn(v[0], v[1]); u.x = *(uint32_t*)&h;
    h = __floats2half2_rn(v[2], v[3]); u.y = *(uint32_t*)&h;
    h = __floats2half2_rn(v[4], v[5]); u.z = *(uint32_t*)&h;
    h = __floats2half2_rn(v[6], v[7]); u.w = *(uint32_t*)&h;
    *(uint4*)((char*)g_Lh + (kd * D + ep) * 2) = u;
}

// ---------------------------------------------------------------------------
__global__ void __launch_bounds__(256)
build_Xh(const float* __restrict__ X) {
    const int i = (blockIdx.x * 256 + threadIdx.x) * 4;   // 1024*512
    float4 x = *(const float4*)&X[i];
    __half2 h0 = __floats2half2_rn(x.x, x.y);
    __half2 h1 = __floats2half2_rn(x.z, x.w);
    *(uint2*)((char*)g_Xh + i * 2) = make_uint2(*(uint32_t*)&h0, *(uint32_t*)&h1);
}

// ---------------------------------------------------------------------------
__global__ void __launch_bounds__(512)
build_wL(const float* __restrict__ W) {
    __shared__ float ws[512];
    const int k = blockIdx.x, e = threadIdx.x;
    ws[e] = W[(size_t)k * D + e];
    __syncthreads();
    const __half* Lk = g_Lh + (size_t)k * D * D;
    float s = 0.f;
    const int dstart = (e >> 7) << 7;
#pragma unroll 4
    for (int d = dstart; d < D; ++d)
        s += ws[d] * __half2float(Lk[(size_t)d * D + e]);
    g_wL[(size_t)k * D + e] = s;
}

// ---------------------------------------------------------------------------
// Main GEMM: Q = Xh @ Lh block; epilogue squares (Q - wL[e]) and row-reduces.
// K-chunks of 64, 3 SMEM stages, one cp.async group per chunk, wait_group 1.
// A stage: 128 rows x 64 halfs, stride 144 B. B: 64 rows x 128 halfs, 272 B.
// ---------------------------------------------------------------------------
#define ROFF   0
#define WLOFF  2048
#define STG0   2560
#define ASZ    18432                          /* 128 * 144 */
#define BSZ    17408                          /* 64 * 272 */
#define STGSZ  (ASZ + BSZ)                    /* 35840 */
#define SMEMSZ (2560 + 3 * 35840)             /* 110080 */

__global__ void __launch_bounds__(256, 2)
gml2_mma() {
    extern __shared__ char smem[];
    const int tid = threadIdx.x;
    const int wid = tid >> 5, lid = tid & 31;
    const int b0 = blockIdx.x * 128;
    const int k  = blockIdx.y;
    const int j  = blockIdx.z;
    const int e0 = j << 7;
    const int nc = 8 - (j << 1);              // K-chunks of 64: d in [e0, 512)

    const uint32_t sbase = smem_u32(smem);
    float* wLs = (float*)(smem + WLOFF);
    if (tid < 128) wLs[tid] = g_wL[(size_t)k * D + e0 + tid];

    const __half* Bk = g_Lh + (size_t)k * D * D;   // [d][e]
    const __half* Ab = g_Xh + (size_t)b0 * D;

    // ---- stage fill helper (macro to keep addresses simple)
#define ISSUE_CHUNK(cc, st) do {                                            \
        const int d0_ = e0 + (cc) * 64;                                     \
        const uint32_t as_ = sbase + STG0 + (st) * STGSZ;                   \
        const uint32_t bs_ = as_ + ASZ;                                     \
        _Pragma("unroll")                                                   \
        for (int it = 0; it < 4; ++it) {  /* A: 128 rows x 8 segs */        \
            const int idx = it * 256 + tid;                                 \
            const int row = idx >> 3, seg = idx & 7;                        \
            cpasync16(as_ + row * 144 + seg * 16,                           \
                      Ab + (size_t)row * D + d0_ + seg * 8);                \
        }                                                                   \
        _Pragma("unroll")                                                   \
        for (int it = 0; it < 4; ++it) {  /* B: 64 rows x 16 segs */        \
            const int idx = it * 256 + tid;                                 \
            const int rl = idx >> 4, seg = idx & 15;                        \
            cpasync16(bs_ + rl * 272 + seg * 16,                            \
                      Bk + (size_t)(d0_ + rl) * D + e0 + seg * 8);          \
        }                                                                   \
    } while (0)

    // ---- prologue: issue chunks 0,1
    ISSUE_CHUNK(0, 0);
    asm volatile("cp.async.commit_group;" ::: "memory");
    if (nc > 1) ISSUE_CHUNK(1, 1);
    asm volatile("cp.async.commit_group;" ::: "memory");

    float acc[2][8][4];
#pragma unroll
    for (int mt = 0; mt < 2; ++mt)
#pragma unroll
        for (int nt = 0; nt < 8; ++nt)
#pragma unroll
            for (int q = 0; q < 4; ++q) acc[mt][nt][q] = 0.f;

    const int m0 = (wid & 3) * 32, n0 = (wid >> 2) * 64;
    const uint32_t aL = sbase + STG0 + (m0 + (lid & 15)) * 144 + (lid >> 4) * 16;
    const uint32_t bL = sbase + STG0 + ASZ +
                        (lid & 15) * 272 + (lid >> 4) * 16 + n0 * 2;

    int st = 0;
    for (int c = 0; c < nc; ++c) {
        asm volatile("cp.async.wait_group 1;" ::: "memory");
        __syncthreads();

        if (c + 2 < nc) {
            const int st2 = (st + 2 >= 3) ? st - 1 : st + 2;
            ISSUE_CHUNK(c + 2, st2);
        }
        asm volatile("cp.async.commit_group;" ::: "memory");

        // ---- compute chunk c; triangular warp skip (chunk 0, upper half)
        if (!(n0 == 64 && c == 0)) {
            const uint32_t aB = aL + st * STGSZ;
            const uint32_t bB = bL + st * STGSZ;
#pragma unroll
            for (int ks = 0; ks < 4; ++ks) {
                uint32_t a[2][4], b[8][2];
#pragma unroll
                for (int mt = 0; mt < 2; ++mt)
                    LDSM4(a[mt][0], a[mt][1], a[mt][2], a[mt][3],
                          aB + mt * (16 * 144) + ks * 32);
#pragma unroll
                for (int nt2 = 0; nt2 < 4; ++nt2)
                    LDSM4T(b[nt2 * 2][0], b[nt2 * 2][1],
                           b[nt2 * 2 + 1][0], b[nt2 * 2 + 1][1],
                           bB + ks * (16 * 272) + nt2 * 32);
#pragma unroll
                for (int mt = 0; mt < 2; ++mt)
#pragma unroll
                    for (int nt = 0; nt < 8; ++nt)
                        asm volatile(
                            "mma.sync.aligned.m16n8k16.row.col.f32.f16.f16.f32 "
                            "{%0,%1,%2,%3},{%4,%5,%6,%7},{%8,%9},{%0,%1,%2,%3};"
                            : "+f"(acc[mt][nt][0]), "+f"(acc[mt][nt][1]),
                              "+f"(acc[mt][nt][2]), "+f"(acc[mt][nt][3])
                            : "r"(a[mt][0]), "r"(a[mt][1]),
                              "r"(a[mt][2]), "r"(a[mt][3]),
                              "r"(b[nt][0]), "r"(b[nt][1]));
            }
        }
        st = (st == 2) ? 0 : st + 1;
    }

    // ---- epilogue: subtract wL, square, row-reduce
    const int gq = lid >> 2, tg = lid & 3;
    float q[4];
#pragma unroll
    for (int mt = 0; mt < 2; ++mt) {
        float s0 = 0.f, s1 = 0.f;
#pragma unroll
        for (int nt = 0; nt < 8; ++nt) {
            const int c0 = n0 + nt * 8 + tg * 2;
            const float wl0 = wLs[c0], wl1 = wLs[c0 + 1];
            float p0 = acc[mt][nt][0] - wl0;
            float p1 = acc[mt][nt][1] - wl1;
            float p2 = acc[mt][nt][2] - wl0;
            float p3 = acc[mt][nt][3] - wl1;
            s0 += p0 * p0 + p1 * p1;
            s1 += p2 * p2 + p3 * p3;
        }
        q[mt * 2 + 0] = s0;   // row m0 + 16*mt + gq
        q[mt * 2 + 1] = s1;   // row m0 + 16*mt + gq + 8
    }
#pragma unroll
    for (int i = 0; i < 4; ++i) {
        q[i] += __shfl_xor_sync(0xffffffffu, q[i], 1);
        q[i] += __shfl_xor_sync(0xffffffffu, q[i], 2);
    }
    float* red = (float*)(smem + ROFF);
    __syncthreads();
    if (tg == 0) {
        const int wn = wid >> 2;
        const int rr = m0 + gq;
        red[wn * 128 + rr +  0] = q[0];
        red[wn * 128 + rr +  8] = q[1];
        red[wn * 128 + rr + 16] = q[2];
        red[wn * 128 + rr + 24] = q[3];
    }
    __syncthreads();
    if (tid < 128) {
        float s = red[tid] + red[128 + tid];
        g_part[((size_t)j * 1024 + b0 + tid) * KC + k] = s;
    }
#undef ISSUE_CHUNK
}

// ---------------------------------------------------------------------------
__global__ void finalize(float* __restrict__ out) {
    const size_t idx = (size_t)blockIdx.x * 256 + threadIdx.x;  // 1024*256
    float s = g_part[idx] + g_part[262144 + idx] +
              g_part[2 * 262144 + idx] + g_part[3 * 262144 + idx];
    out[idx] = sqrtf(s);
}

// ---------------------------------------------------------------------------
extern "C" void kernel_launch(void* const* d_in, const int* in_sizes, int n_in,
                              void* d_out, int out_size) {
    const float* X     = (const float*)d_in[0];  // [1024, 512]
    const float* W     = (const float*)d_in[1];  // [256, 1, 512]
    const float* diags = (const float*)d_in[2];  // [256, 512]
    const float* lower = (const float*)d_in[3];  // [256, 130816]
    float* out = (float*)d_out;                  // [1024, 256]

    build_Lh<<<(KC * D * 64) / 256, 256>>>(diags, lower);
    build_Xh<<<(1024 * D / 4) / 256, 256>>>(X);
    build_wL<<<KC, 512>>>(W);

    cudaFuncSetAttribute(gml2_mma, cudaFuncAttributeMaxDynamicSharedMemorySize,
                         SMEMSZ);
    dim3 grid(8, KC, 4);
    gml2_mma<<<grid, 256, SMEMSZ>>>();

    finalize<<<1024, 256>>>(out);
}